// round 13
// baseline (speedup 1.0000x reference)
#include <cuda_runtime.h>
#include <cstdint>
#include <cstddef>

// ---------------------------------------------------------------------------
// DSDM classifier via mma.sync FP8 e4m3 (m16n8k32), 512 threads:
//   S = x . A^T ; w = exp(-sqrt(|x|^2+|A|^2-2S)/T) ; out = (W.M)/rowsum(W)
// x[2048,128], A[100000,128], M[100000,100], out[2048,100], T=2.
// Norms fp32-exact; x/A/M/W quantized e4m3. W carries a constant 2^11 shift
// (cancels in the final num/den division) to stay inside e4m3 dynamic range.
// 16 warps = 8 m-groups x 2 n/k-halves; W goes through a warp-private smem
// tile to form GEMM2 k32 A-fragments. k-split partials -> deterministic reduce.
// ---------------------------------------------------------------------------

#define CONST_B   2048
#define CONST_D   128
#define CONST_N   100000
#define CONST_C   100

#define NSPLIT    9
#define NSPLIT2   18                  // NSPLIT * 2 (k-halves)
#define NPER      11136               // 87 * 128
#define NPAD      100096              // 782 * 128
#define THREADS   512
#define PSTRIDE   112
#define CT        104                 // staged class rows (>=101 needed)

// -(1 / (T * ln2)), T = 2 ; WSHIFT folded into exp2 (cancels in division)
#define NEG_K     (-0.72134752044448169f)
#define WSHIFT    (11.0f)

// smem byte offsets (fp8: every tile is 128 B wide, SW128)
#define SM_XN     0                   // float[128]
#define SM_AN     512                 // 2 bufs x 128 floats -> 1536
#define SM_X      2048                // 128 x 128 B (x tile, e4m3)
#define SM_W      18432               // 128 x 128 B (weights, e4m3)
#define SM_A      34816               // 2 bufs x 16384 (A chunk)
#define SM_MT     67584               // 2 bufs x 13312 (Mt chunk, 104 rows)
#define SM_TOTAL  94208

// device scratch (allocation-free)
__device__ float g_anorm[NPAD];
__device__ __align__(256) unsigned char g_A8[(size_t)CONST_N * CONST_D];
__device__ __align__(256) unsigned char g_Mt8[(size_t)CT * NPAD];
__device__ float g_part[(size_t)NSPLIT2 * CONST_B * PSTRIDE];

// ---------------- asm helpers ----------------
__device__ __forceinline__ uint32_t smem_u32(const void* p) {
    uint32_t a;
    asm("{ .reg .u64 t; cvta.to.shared.u64 t, %1; cvt.u32.u64 %0, t; }"
        : "=r"(a) : "l"(p));
    return a;
}
// pack 4 floats -> 4 e4m3 bytes (f0 in byte0)
__device__ __forceinline__ uint32_t fp8pack4(float f0, float f1, float f2, float f3) {
    uint32_t r;
    asm("{ .reg .b16 lo, hi;\n\t"
        "cvt.rn.satfinite.e4m3x2.f32 lo, %2, %1;\n\t"
        "cvt.rn.satfinite.e4m3x2.f32 hi, %4, %3;\n\t"
        "mov.b32 %0, {lo, hi}; }"
        : "=r"(r) : "f"(f0), "f"(f1), "f"(f2), "f"(f3));
    return r;
}
// pack 2 floats -> 2 e4m3 bytes in a b16 (lo in byte0)
__device__ __forceinline__ unsigned short fp8pack2(float lo, float hi) {
    unsigned short r;
    asm("cvt.rn.satfinite.e4m3x2.f32 %0, %1, %2;" : "=h"(r) : "f"(hi), "f"(lo));
    return r;
}
__device__ __forceinline__ float fsqrt_a(float x) {
    float r; asm("sqrt.approx.f32 %0, %1;" : "=f"(r) : "f"(x)); return r;
}
__device__ __forceinline__ float fex2(float x) {
    float r; asm("ex2.approx.f32 %0, %1;" : "=f"(r) : "f"(x)); return r;
}
__device__ __forceinline__ void ldsm4(uint32_t* r, uint32_t addr) {
    asm volatile("ldmatrix.sync.aligned.m8n8.x4.shared.b16 {%0,%1,%2,%3}, [%4];"
                 : "=r"(r[0]), "=r"(r[1]), "=r"(r[2]), "=r"(r[3]) : "r"(addr));
}
__device__ __forceinline__ void ldsm2(uint32_t* r, uint32_t addr) {
    asm volatile("ldmatrix.sync.aligned.m8n8.x2.shared.b16 {%0,%1}, [%2];"
                 : "=r"(r[0]), "=r"(r[1]) : "r"(addr));
}
__device__ __forceinline__ void mma_fp8(float* c, const uint32_t* a,
                                        uint32_t b0, uint32_t b1) {
    asm volatile(
        "mma.sync.aligned.m16n8k32.row.col.f32.e4m3.e4m3.f32 "
        "{%0,%1,%2,%3}, {%4,%5,%6,%7}, {%8,%9}, {%0,%1,%2,%3};"
        : "+f"(c[0]), "+f"(c[1]), "+f"(c[2]), "+f"(c[3])
        : "r"(a[0]), "r"(a[1]), "r"(a[2]), "r"(a[3]), "r"(b0), "r"(b1));
}
__device__ __forceinline__ void cpasync16(uint32_t dst, const void* src) {
    asm volatile("cp.async.cg.shared.global [%0], [%1], 16;"
                 :: "r"(dst), "l"(src) : "memory");
}
__device__ __forceinline__ void sts16(uint32_t addr, unsigned short v) {
    asm volatile("st.shared.u16 [%0], %1;" :: "r"(addr), "h"(v) : "memory");
}
#define CP_COMMIT asm volatile("cp.async.commit_group;" ::: "memory")
#define CP_WAIT1  asm volatile("cp.async.wait_group 1;" ::: "memory")
#define CP_WAIT0  asm volatile("cp.async.wait_group 0;" ::: "memory")

// ---------------------------------------------------------------------------
// prep_A: |A_n|^2 fp32 + A -> e4m3; padding rows get anorm = 1e30 (w = 0).
// ---------------------------------------------------------------------------
__global__ void prep_A(const float* __restrict__ A) {
    int row  = blockIdx.x * 8 + (threadIdx.x >> 5);
    int lane = threadIdx.x & 31;
    if (row >= NPAD) return;
    if (row >= CONST_N) {
        if (lane == 0) g_anorm[row] = 1e30f;
        return;
    }
    float4 v = reinterpret_cast<const float4*>(A + (size_t)row * CONST_D)[lane];
    float s = v.x * v.x + v.y * v.y + v.z * v.z + v.w * v.w;
    #pragma unroll
    for (int o = 16; o; o >>= 1) s += __shfl_xor_sync(0xffffffffu, s, o);
    if (lane == 0) g_anorm[row] = s;
    reinterpret_cast<uint32_t*>(g_A8 + (size_t)row * CONST_D)[lane] =
        fp8pack4(v.x, v.y, v.z, v.w);
}

// ---------------------------------------------------------------------------
// prep_Mt: M[n][c] fp32 -> g_Mt8[c][n] e4m3, row 100 = 1.0, rows 101-103 = 0.
// ---------------------------------------------------------------------------
__global__ void prep_Mt(const float* __restrict__ M) {
    extern __shared__ float st[];     // [128][104]
    const int tid = threadIdx.x;
    const int t0  = blockIdx.x * 128;
    for (int idx = tid; idx < 128 * 25; idx += 256) {
        int r = idx / 25, q = idx % 25;
        int n = t0 + r;
        float4 v = make_float4(0.f, 0.f, 0.f, 0.f);
        if (n < CONST_N)
            v = reinterpret_cast<const float4*>(M + (size_t)n * CONST_C)[q];
        st[r * 104 + q * 4 + 0] = v.x;
        st[r * 104 + q * 4 + 1] = v.y;
        st[r * 104 + q * 4 + 2] = v.z;
        st[r * 104 + q * 4 + 3] = v.w;
    }
    __syncthreads();
    for (int idx = tid; idx < CT * 32; idx += 256) {
        int c = idx >> 5, nq = idx & 31;
        float f[4];
        #pragma unroll
        for (int j = 0; j < 4; j++) {
            int nl = nq * 4 + j;
            if (c < CONST_C)        f[j] = st[nl * 104 + c];
            else if (c == CONST_C)  f[j] = (t0 + nl < CONST_N) ? 1.f : 0.f;
            else                    f[j] = 0.f;
        }
        reinterpret_cast<uint32_t*>(g_Mt8 + (size_t)c * NPAD + t0)[nq] =
            fp8pack4(f[0], f[1], f[2], f[3]);
    }
}

// ---------------------------------------------------------------------------
// cp.async staging of one 128-address chunk (fp8: ~30 KB total).
// ---------------------------------------------------------------------------
__device__ __forceinline__ void stage_chunk(uint32_t sb, int n0, int nEnd,
                                            int buf, int tid) {
    const int q = tid & 3;             // 32-byte quarter of a 128-B row
    {   // A chunk: row nl (0..127)
        int nl = tid >> 2;
        int nIdx = n0 + nl; if (nIdx >= nEnd) nIdx = nEnd - 1;
        const char* src = (const char*)(g_A8 + (size_t)nIdx * CONST_D) + 32 * q;
        uint32_t dst = sb + SM_A + buf * 16384 + (uint32_t)nl * 128;
        uint32_t sw = (uint32_t)(nl & 7) << 4;
        cpasync16(dst + (((uint32_t)(32 * q))      ^ sw), src);
        cpasync16(dst + (((uint32_t)(32 * q + 16)) ^ sw), src + 16);
    }
    {   // Mt chunk: class row c (< CT)
        int c = tid >> 2;
        if (c < CT) {
            const char* src = (const char*)(g_Mt8 + (size_t)c * NPAD + n0) + 32 * q;
            uint32_t dst = sb + SM_MT + buf * 13312 + (uint32_t)c * 128;
            uint32_t sw = (uint32_t)(c & 7) << 4;
            cpasync16(dst + (((uint32_t)(32 * q))      ^ sw), src);
            cpasync16(dst + (((uint32_t)(32 * q + 16)) ^ sw), src + 16);
        }
    }
    if (tid < 32)   // anorms (padded with 1e30 -> w=0, no OOB)
        cpasync16(sb + SM_AN + buf * 512 + tid * 16,
                  (const char*)(g_anorm + n0) + tid * 16);
}

// ---------------------------------------------------------------------------
// main fused kernel: grid (16, 9), 512 threads = 8 m-groups x 2 n/k-halves.
// ---------------------------------------------------------------------------
__global__ void __launch_bounds__(THREADS, 1)
dsdm_mma(const float* __restrict__ x)
{
    extern __shared__ char smem[];
    const uint32_t sb = smem_u32(smem);
    const int tid  = threadIdx.x;
    const int warp = tid >> 5, lane = tid & 31;
    const int mg   = warp >> 1;        // m-group: rows [16mg, 16mg+16)
    const int ng   = warp & 1;         // n/k half
    const int m0   = mg * 16;
    const int b0   = blockIdx.x * 128;
    const int split = blockIdx.y;
    const int nBeg = split * NPER;
    const int nEnd = (nBeg + NPER < CONST_N) ? nBeg + NPER : CONST_N;
    const int nchunks = (nEnd - nBeg + 127) >> 7;

    float* xn_s = reinterpret_cast<float*>(smem + SM_XN);

    // ---- stage x tile (e4m3, SW128) + fp32 row norms ----
    for (int r = warp; r < 128; r += 16) {
        float4 v = reinterpret_cast<const float4*>(x + (size_t)(b0 + r) * CONST_D)[lane];
        float sq = v.x * v.x + v.y * v.y + v.z * v.z + v.w * v.w;
        #pragma unroll
        for (int o = 16; o; o >>= 1) sq += __shfl_xor_sync(0xffffffffu, sq, o);
        if (lane == 0) xn_s[r] = sq;
        uint32_t pk = fp8pack4(v.x, v.y, v.z, v.w);
        uint32_t off = ((uint32_t)(lane * 4)) ^ ((uint32_t)(r & 7) << 4);
        *reinterpret_cast<uint32_t*>(smem + SM_X + (uint32_t)r * 128 + off) = pk;
    }

    // prefetch chunk 0
    stage_chunk(sb, nBeg, nEnd, 0, tid);
    CP_COMMIT;
    __syncthreads();

    // ---- X fragments: 16m x 128k e4m3 A-operands (4 k32 groups x 4 regs) ----
    const int aRow = (lane & 7) + ((lane >> 3) & 1) * 8;
    const uint32_t aswr = (uint32_t)(aRow & 7) << 4;
    uint32_t xa[4][4];
    {
        uint32_t rb = sb + SM_X + (uint32_t)(m0 + aRow) * 128;
        #pragma unroll
        for (int kk = 0; kk < 4; kk++) {
            uint32_t col = ((uint32_t)(32 * kk + (lane >> 4) * 16)) ^ aswr;
            ldsm4(xa[kk], rb + col);
        }
    }
    const float xn0 = xn_s[m0 + (lane >> 2)];
    const float xn1 = xn_s[m0 + 8 + (lane >> 2)];

    // B-operand ldmatrix lane map (rows via bit4, k-16B-half via bit3)
    const int bRow = (lane & 7) + ((lane >> 4) & 1) * 8;
    const uint32_t bKb = ((uint32_t)(lane >> 3) & 1) * 16;
    const uint32_t bsw = (uint32_t)(bRow & 7) << 4;

    const int t4 = lane & 3;
    const int t4x2 = t4 * 2;

    // W smem addresses (warp-private block: rows m0..m0+15, cols 64ng..+63)
    const uint32_t wRowLo = (uint32_t)(m0 + (lane >> 2));
    const uint32_t wSw    = (uint32_t)((lane >> 2) & 7) << 4;
    const uint32_t wBase  = sb + SM_W + wRowLo * 128;

    float acc[13][4];                  // 16m x 104c k-partial
    #pragma unroll
    for (int j = 0; j < 13; j++)
        #pragma unroll
        for (int qq = 0; qq < 4; qq++) acc[j][qq] = 0.f;

    for (int ch = 0; ch < nchunks; ch++) {
        if (ch + 1 < nchunks) {
            stage_chunk(sb, nBeg + (ch + 1) * 128, nEnd, (ch + 1) & 1, tid);
            CP_COMMIT;
            CP_WAIT1;
        } else {
            CP_WAIT0;
        }
        __syncthreads();

        const int buf = ch & 1;
        const uint32_t aTile = sb + SM_A + buf * 16384;
        const uint32_t mTile = sb + SM_MT + buf * 13312;
        const float* an_b = reinterpret_cast<const float*>(smem + SM_AN + buf * 512);

        // ---- GEMM1 + epilogue per 16-n slice; W -> smem (e4m3) ----
        #pragma unroll
        for (int g = 0; g < 4; g++) {
            const int nb = 64 * ng + 16 * g;
            float sacc[2][4];
            #pragma unroll
            for (int j = 0; j < 2; j++)
                #pragma unroll
                for (int qq = 0; qq < 4; qq++) sacc[j][qq] = 0.f;
            {
                const uint32_t rowb = aTile + (uint32_t)(nb + bRow) * 128;
                #pragma unroll
                for (int kk = 0; kk < 4; kk++) {
                    uint32_t b4[4];
                    ldsm4(b4, rowb + (((uint32_t)(32 * kk) + bKb) ^ bsw));
                    // r0=[n-low,k-low] r1=[n-low,k-high] r2=[n-high,k-low] r3=[n-high,k-high]
                    mma_fp8(sacc[0], xa[kk], b4[0], b4[1]);
                    mma_fp8(sacc[1], xa[kk], b4[2], b4[3]);
                }
            }

            // epilogue: w' = exp2(WSHIFT - K*dist) -> e4m3 pairs into W smem
            #pragma unroll
            for (int j = 0; j < 2; j++) {
                float2 anv = *reinterpret_cast<const float2*>(
                    an_b + nb + 8 * j + t4x2);
                float q0 = fmaxf(fmaf(-2.f, sacc[j][0], xn0 + anv.x), 0.f);
                float q1 = fmaxf(fmaf(-2.f, sacc[j][1], xn0 + anv.y), 0.f);
                float q2 = fmaxf(fmaf(-2.f, sacc[j][2], xn1 + anv.x), 0.f);
                float q3 = fmaxf(fmaf(-2.f, sacc[j][3], xn1 + anv.y), 0.f);
                float w0 = fex2(fmaf(NEG_K, fsqrt_a(q0), WSHIFT));
                float w1 = fex2(fmaf(NEG_K, fsqrt_a(q1), WSHIFT));
                float w2 = fex2(fmaf(NEG_K, fsqrt_a(q2), WSHIFT));
                float w3 = fex2(fmaf(NEG_K, fsqrt_a(q3), WSHIFT));
                uint32_t col = ((uint32_t)(nb + 8 * j + t4x2)) ^ wSw;
                sts16(wBase + col,        fp8pack2(w0, w1));
                sts16(wBase + 1024 + col, fp8pack2(w2, w3));   // m+8 rows
            }
        }
        __syncwarp();

        // ---- W A-fragments from smem (16m x 64k e4m3, 2 k32 groups) ----
        uint32_t wf[2][4];
        {
            uint32_t rb = sb + SM_W + (uint32_t)(m0 + aRow) * 128;
            #pragma unroll
            for (int kk2 = 0; kk2 < 2; kk2++) {
                uint32_t col = ((uint32_t)(64 * ng + 32 * kk2 + (lane >> 4) * 16)) ^ aswr;
                ldsm4(wf[kk2], rb + col);
            }
        }

        // ---- GEMM2: ACC += W . Mt^T over this warp's 64-k half ----
        #pragma unroll
        for (int kk2 = 0; kk2 < 2; kk2++) {
            const uint32_t colk = ((uint32_t)(64 * ng + 32 * kk2) + bKb) ^ bsw;
            #pragma unroll
            for (int Jp = 0; Jp < 6; Jp++) {     // class octs 2Jp, 2Jp+1
                uint32_t b4[4];
                ldsm4(b4, mTile + (uint32_t)(16 * Jp + bRow) * 128 + colk);
                mma_fp8(acc[2 * Jp],     wf[kk2], b4[0], b4[1]);
                mma_fp8(acc[2 * Jp + 1], wf[kk2], b4[2], b4[3]);
            }
            {   // class oct 12 (rows 96-103): x2
                uint32_t b2[2];
                uint32_t row12 = (uint32_t)(96 + (lane & 7));
                uint32_t c12 = ((uint32_t)(64 * ng + 32 * kk2) +
                                ((uint32_t)(lane >> 3) & 1) * 16) ^
                               (((uint32_t)(lane & 7) & 7) << 4);
                ldsm2(b2, mTile + row12 * 128 + c12);
                mma_fp8(acc[12], wf[kk2], b2[0], b2[1]);
            }
        }
        __syncthreads();
    }

    // ---- write k-split partials: slice = split*2 + ng ----
    {
        const int sp2 = split * 2 + ng;
        int rA = b0 + m0 + (lane >> 2);
        size_t baseA = ((size_t)sp2 * CONST_B + rA) * PSTRIDE;
        size_t baseB = baseA + (size_t)8 * PSTRIDE;
        #pragma unroll
        for (int jt = 0; jt < 13; jt++) {
            int c = 8 * jt + t4x2;
            if (c <= CONST_C) {
                g_part[baseA + c] = acc[jt][0];
                g_part[baseB + c] = acc[jt][2];
            }
            if (c + 1 <= CONST_C) {
                g_part[baseA + c + 1] = acc[jt][1];
                g_part[baseB + c + 1] = acc[jt][3];
            }
        }
    }
}

// ---------------------------------------------------------------------------
// reduce: deterministic sum over 18 partial slices + normalize.
// (2^WSHIFT scaling of W cancels in num/den.)
// ---------------------------------------------------------------------------
__global__ void reduce_kernel(float* __restrict__ out) {
    int i = blockIdx.x * blockDim.x + threadIdx.x;
    if (i >= CONST_B * CONST_C) return;
    int b = i / CONST_C, c = i % CONST_C;
    float num = 0.f, den = 0.f;
    #pragma unroll
    for (int s = 0; s < NSPLIT2; s++) {
        const float* p = g_part + ((size_t)s * CONST_B + b) * PSTRIDE;
        num += p[c];
        den += p[CONST_C];
    }
    out[i] = num / den;
}

// ---------------------------------------------------------------------------
extern "C" void kernel_launch(void* const* d_in, const int* in_sizes, int n_in,
                              void* d_out, int out_size)
{
    const float* x = (const float*)d_in[0];   // [2048, 128]
    const float* A = (const float*)d_in[1];   // [100000, 128]
    const float* M = (const float*)d_in[2];   // [100000, 100]
    float* out = (float*)d_out;               // [2048, 100]

    cudaFuncSetAttribute(dsdm_mma, cudaFuncAttributeMaxDynamicSharedMemorySize,
                         SM_TOTAL);
    cudaFuncSetAttribute(prep_Mt, cudaFuncAttributeMaxDynamicSharedMemorySize,
                         128 * 104 * 4);

    prep_A<<<NPAD / 8, 256>>>(A);
    prep_Mt<<<NPAD / 128, 256, 128 * 104 * 4>>>(M);
    dsdm_mma<<<dim3(CONST_B / 128, NSPLIT), THREADS, SM_TOTAL>>>(x);
    reduce_kernel<<<(CONST_B * CONST_C + 255) / 256, 256>>>(out);
}

// round 14
// speedup vs baseline: 1.2234x; 1.2234x over previous
#include <cuda_runtime.h>
#include <cstdint>
#include <cstddef>

// ---------------------------------------------------------------------------
// DSDM classifier via mma.sync bf16, 512 threads (16 warps = 8 mg x 2 ng):
//   S = x . A^T ; w = exp(-sqrt(|x|^2+|A|^2-2S)/T) ; out = (W.M)/rowsum(W)
// x[2048,128], A[100000,128], M[100000,100], out[2048,100], T=2.
// Per warp: 16 m-rows, one 64-n half of GEMM1, matching 64-k half of GEMM2.
// B fragments double-buffered in registers so LDSM latency hides under HMMA.
// W register-resident; k-split partials -> deterministic reduce.
// Prep passes (A norms/bf16 + Mt transpose) fused into one launch.
// ---------------------------------------------------------------------------

#define CONST_B   2048
#define CONST_D   128
#define CONST_N   100000
#define CONST_C   100

#define NSPLIT    9
#define NSPLIT2   18                  // NSPLIT * 2 (k-halves)
#define NPER      11136               // 87 * 128
#define NPAD      100096              // 782 * 128
#define THREADS   512
#define PSTRIDE   112
#define CT        104                 // staged class rows (>=101 needed)

#define NA_BLOCKS  (NPAD / 8)         // 12512 A-prep blocks
#define NMT_BLOCKS (NPAD / 128)       // 782 Mt-prep blocks

// -(1 / (T * ln2)), T = 2
#define NEG_K     (-0.72134752044448169f)

// smem byte offsets
#define SM_XN     0                   // float[128]
#define SM_AN     512                 // 2 bufs x 128 floats
#define SM_X      2048                // 2 halves x 16384 (x tile, bf16 SW128)
#define SM_A      34816               // 2 bufs x (2 halves x 16384)
#define SM_MT     100352              // 2 bufs x (2 halves x 16384)
#define SM_TOTAL  165888

#define SWZ(b)    ((b) ^ (((b) >> 3) & 0x70))

// device scratch (allocation-free)
__device__ float g_anorm[NPAD];
__device__ __align__(256) unsigned short g_Abf[(size_t)CONST_N * CONST_D];
__device__ __align__(256) unsigned short g_Mt[(size_t)128 * NPAD];
__device__ float g_part[(size_t)NSPLIT2 * CONST_B * PSTRIDE];

// ---------------- asm helpers ----------------
__device__ __forceinline__ uint32_t smem_u32(const void* p) {
    uint32_t a;
    asm("{ .reg .u64 t; cvta.to.shared.u64 t, %1; cvt.u32.u64 %0, t; }"
        : "=r"(a) : "l"(p));
    return a;
}
__device__ __forceinline__ uint32_t bfpack(float lo, float hi) {
    uint32_t r;
    asm("cvt.rn.bf16x2.f32 %0, %1, %2;" : "=r"(r) : "f"(hi), "f"(lo));
    return r;
}
__device__ __forceinline__ float fsqrt_a(float x) {
    float r; asm("sqrt.approx.f32 %0, %1;" : "=f"(r) : "f"(x)); return r;
}
__device__ __forceinline__ float fex2(float x) {
    float r; asm("ex2.approx.f32 %0, %1;" : "=f"(r) : "f"(x)); return r;
}
__device__ __forceinline__ void ldsm4(uint32_t* r, uint32_t addr) {
    asm volatile("ldmatrix.sync.aligned.m8n8.x4.shared.b16 {%0,%1,%2,%3}, [%4];"
                 : "=r"(r[0]), "=r"(r[1]), "=r"(r[2]), "=r"(r[3]) : "r"(addr));
}
__device__ __forceinline__ void mma16816(float* c, const uint32_t* a,
                                         uint32_t b0, uint32_t b1) {
    asm volatile(
        "mma.sync.aligned.m16n8k16.row.col.f32.bf16.bf16.f32 "
        "{%0,%1,%2,%3}, {%4,%5,%6,%7}, {%8,%9}, {%0,%1,%2,%3};"
        : "+f"(c[0]), "+f"(c[1]), "+f"(c[2]), "+f"(c[3])
        : "r"(a[0]), "r"(a[1]), "r"(a[2]), "r"(a[3]), "r"(b0), "r"(b1));
}
__device__ __forceinline__ void cpasync16(uint32_t dst, const void* src) {
    asm volatile("cp.async.cg.shared.global [%0], [%1], 16;"
                 :: "r"(dst), "l"(src) : "memory");
}
#define CP_COMMIT asm volatile("cp.async.commit_group;" ::: "memory")
#define CP_WAIT1  asm volatile("cp.async.wait_group 1;" ::: "memory")
#define CP_WAIT0  asm volatile("cp.async.wait_group 0;" ::: "memory")

// ---------------------------------------------------------------------------
// prep_AM: fused prep. Blocks [0, NA_BLOCKS): |A_n|^2 fp32 + A -> bf16
// (padding rows get anorm = 1e30 -> w = 0). Blocks [NA_BLOCKS, +NMT_BLOCKS):
// M[n][c] fp32 -> g_Mt[c][n] bf16, row 100 = 1.0, zero padding.
// ---------------------------------------------------------------------------
__global__ void prep_AM(const float* __restrict__ A, const float* __restrict__ M) {
    extern __shared__ float st[];     // Mt branch: [128][104]
    if (blockIdx.x < NA_BLOCKS) {
        int row  = blockIdx.x * 8 + (threadIdx.x >> 5);
        int lane = threadIdx.x & 31;
        if (row >= NPAD) return;
        if (row >= CONST_N) {
            if (lane == 0) g_anorm[row] = 1e30f;
            return;
        }
        float4 v = reinterpret_cast<const float4*>(A + (size_t)row * CONST_D)[lane];
        float s = v.x * v.x + v.y * v.y + v.z * v.z + v.w * v.w;
        #pragma unroll
        for (int o = 16; o; o >>= 1) s += __shfl_xor_sync(0xffffffffu, s, o);
        if (lane == 0) g_anorm[row] = s;
        uint2 p = make_uint2(bfpack(v.x, v.y), bfpack(v.z, v.w));
        reinterpret_cast<uint2*>(g_Abf + (size_t)row * CONST_D)[lane] = p;
        return;
    }
    // ---- Mt transpose branch ----
    const int tid = threadIdx.x;
    const int t0  = (blockIdx.x - NA_BLOCKS) * 128;
    for (int idx = tid; idx < 128 * 25; idx += 256) {
        int r = idx / 25, q = idx % 25;
        int n = t0 + r;
        float4 v = make_float4(0.f, 0.f, 0.f, 0.f);
        if (n < CONST_N)
            v = reinterpret_cast<const float4*>(M + (size_t)n * CONST_C)[q];
        st[r * 104 + q * 4 + 0] = v.x;
        st[r * 104 + q * 4 + 1] = v.y;
        st[r * 104 + q * 4 + 2] = v.z;
        st[r * 104 + q * 4 + 3] = v.w;
    }
    __syncthreads();
    for (int idx = tid; idx < 128 * 16; idx += 256) {
        int c = idx >> 4, nq = idx & 15;
        uint32_t h[4];
        #pragma unroll
        for (int j = 0; j < 4; j++) {
            int nl = nq * 8 + j * 2;
            float f0, f1;
            if (c < CONST_C) {
                f0 = st[nl * 104 + c];
                f1 = st[(nl + 1) * 104 + c];
            } else if (c == CONST_C) {
                f0 = (t0 + nl     < CONST_N) ? 1.f : 0.f;
                f1 = (t0 + nl + 1 < CONST_N) ? 1.f : 0.f;
            } else { f0 = 0.f; f1 = 0.f; }
            h[j] = bfpack(f0, f1);
        }
        reinterpret_cast<uint4*>(g_Mt + (size_t)c * NPAD + t0)[nq] =
            make_uint4(h[0], h[1], h[2], h[3]);
    }
}

// ---------------------------------------------------------------------------
// cp.async staging of one 128-address chunk (512 threads).
// ---------------------------------------------------------------------------
__device__ __forceinline__ void stage_chunk(uint32_t sb, int n0, int nEnd,
                                            int buf, int tid) {
    const int q  = tid & 3;            // 64-byte quarter of a 256-B row
    const int hf = q >> 1;             // 128-B half
    const uint32_t qoff = (uint32_t)(q & 1) * 64;
    {   // A chunk: row nl (0..127), SW128 within each 128-B half-row
        int nl = tid >> 2;
        int nIdx = n0 + nl; if (nIdx >= nEnd) nIdx = nEnd - 1;
        const char* src = (const char*)(g_Abf + (size_t)nIdx * CONST_D + hf * 64)
                          + qoff;
        uint32_t dst = sb + SM_A + buf * 32768 + hf * 16384 + (uint32_t)nl * 128;
        uint32_t sw = (uint32_t)(nl & 7) << 4;
        #pragma unroll
        for (int j = 0; j < 4; j++)
            cpasync16(dst + ((qoff + (uint32_t)(j * 16)) ^ sw), src + j * 16);
    }
    {   // Mt chunk: class row c (< CT)
        int c = tid >> 2;
        if (c < CT) {
            const char* src = (const char*)(g_Mt + (size_t)c * NPAD + n0 + hf * 64)
                              + qoff;
            uint32_t dst = sb + SM_MT + buf * 32768 + hf * 16384 + (uint32_t)c * 128;
            uint32_t sw = (uint32_t)(c & 7) << 4;
            #pragma unroll
            for (int j = 0; j < 4; j++)
                cpasync16(dst + ((qoff + (uint32_t)(j * 16)) ^ sw), src + j * 16);
        }
    }
    if (tid < 32)   // anorms (padded with 1e30 -> w=0, no OOB)
        cpasync16(sb + SM_AN + buf * 512 + tid * 16,
                  (const char*)(g_anorm + n0) + tid * 16);
}

// ---------------------------------------------------------------------------
// main fused kernel: grid (16, 9), 512 threads = 8 m-groups x 2 n/k-halves.
// ---------------------------------------------------------------------------
__global__ void __launch_bounds__(THREADS, 1)
dsdm_mma(const float* __restrict__ x)
{
    extern __shared__ char smem[];
    const uint32_t sb = smem_u32(smem);
    const int tid  = threadIdx.x;
    const int warp = tid >> 5, lane = tid & 31;
    const int mg   = warp >> 1;        // m-group: rows [16mg, 16mg+16)
    const int ng   = warp & 1;         // n/k half
    const int m0   = mg * 16;
    const int b0   = blockIdx.x * 128;
    const int split = blockIdx.y;
    const int nBeg = split * NPER;
    const int nEnd = (nBeg + NPER < CONST_N) ? nBeg + NPER : CONST_N;
    const int nchunks = (nEnd - nBeg + 127) >> 7;

    float* xn_s = reinterpret_cast<float*>(smem + SM_XN);

    // ---- stage x tile (bf16 SW128 halves) + row norms ----
    for (int r = warp; r < 128; r += 16) {
        float4 v = reinterpret_cast<const float4*>(x + (size_t)(b0 + r) * CONST_D)[lane];
        float sq = v.x * v.x + v.y * v.y + v.z * v.z + v.w * v.w;
        #pragma unroll
        for (int o = 16; o; o >>= 1) sq += __shfl_xor_sync(0xffffffffu, sq, o);
        if (lane == 0) xn_s[r] = sq;
        uint2 p = make_uint2(bfpack(v.x, v.y), bfpack(v.z, v.w));
        uint32_t off = (uint32_t)r * 128 + (lane & 15) * 8;
        *reinterpret_cast<uint2*>(smem + SM_X + (lane >> 4) * 16384 + SWZ(off)) = p;
    }

    // prefetch chunk 0
    stage_chunk(sb, nBeg, nEnd, 0, tid);
    CP_COMMIT;
    __syncthreads();

    // ---- X fragments: 16m x 128k A-operands, register-resident ----
    uint32_t xa[8][4];
    {
        int aRow = (lane & 7) + ((lane >> 3) & 1) * 8;
        int aKb  = (lane >> 4) * 16;
        uint32_t swr = (uint32_t)(aRow & 7) << 4;
        uint32_t rb  = sb + SM_X + (uint32_t)(m0 + aRow) * 128;
        #pragma unroll
        for (int kk = 0; kk < 8; kk++) {
            uint32_t col = (uint32_t)(((32 * kk) & 127) + aKb) ^ swr;
            ldsm4(xa[kk], rb + (kk >> 2) * 16384 + col);
        }
    }
    const float xn0 = xn_s[m0 + (lane >> 2)];
    const float xn1 = xn_s[m0 + 8 + (lane >> 2)];

    // B-operand ldmatrix lane map
    const int bRow = (lane & 7) + ((lane >> 4) & 1) * 8;
    const int bKb  = ((lane >> 3) & 1) * 16;
    const uint32_t bsw = (uint32_t)(bRow & 7) << 4;
    uint32_t bcol[8];
    #pragma unroll
    for (int kk = 0; kk < 8; kk++)
        bcol[kk] = (uint32_t)(((32 * kk) & 127) + bKb) ^ bsw;

    const int t4x2 = (lane & 3) * 2;

    float acc[13][4];                  // 16m x 104c k-partial
    #pragma unroll
    for (int j = 0; j < 13; j++)
        #pragma unroll
        for (int qq = 0; qq < 4; qq++) acc[j][qq] = 0.f;

    for (int ch = 0; ch < nchunks; ch++) {
        if (ch + 1 < nchunks) {
            stage_chunk(sb, nBeg + (ch + 1) * 128, nEnd, (ch + 1) & 1, tid);
            CP_COMMIT;
            CP_WAIT1;
        } else {
            CP_WAIT0;
        }
        __syncthreads();

        const int buf = ch & 1;
        const uint32_t aTile = sb + SM_A + buf * 32768;
        const uint32_t mTile = sb + SM_MT + buf * 32768 + ng * 16384;
        const float* an_b = reinterpret_cast<const float*>(smem + SM_AN + buf * 512);

        #pragma unroll
        for (int g = 0; g < 4; g++) {
            const int nb = 64 * ng + 16 * g;

            // GEMM1 slice: S[16m x 16n] (k = 128), B double-buffered in regs
            float sacc[2][4];
            #pragma unroll
            for (int j = 0; j < 2; j++)
                #pragma unroll
                for (int qq = 0; qq < 4; qq++) sacc[j][qq] = 0.f;
            {
                uint32_t rowb = aTile + (uint32_t)(nb + bRow) * 128;
                uint32_t b4[2][4];
                ldsm4(b4[0], rowb + bcol[0]);
                #pragma unroll
                for (int kk = 0; kk < 8; kk++) {
                    if (kk < 7)
                        ldsm4(b4[(kk + 1) & 1],
                              rowb + ((kk + 1) >> 2) * 16384 + bcol[kk + 1]);
                    const uint32_t* c4 = b4[kk & 1];
                    mma16816(sacc[0], xa[kk], c4[0], c4[1]);
                    mma16816(sacc[1], xa[kk], c4[2], c4[3]);
                }
            }

            // epilogue: w = exp2(-K*sqrt(xn+an-2S)) -> A-frag wfc (regs only)
            uint32_t wfc[4];
            #pragma unroll
            for (int j = 0; j < 2; j++) {
                float2 anv = *reinterpret_cast<const float2*>(an_b + nb + 8 * j + t4x2);
                float q0 = fmaxf(fmaf(-2.f, sacc[j][0], xn0 + anv.x), 0.f);
                float q1 = fmaxf(fmaf(-2.f, sacc[j][1], xn0 + anv.y), 0.f);
                float q2 = fmaxf(fmaf(-2.f, sacc[j][2], xn1 + anv.x), 0.f);
                float q3 = fmaxf(fmaf(-2.f, sacc[j][3], xn1 + anv.y), 0.f);
                float w0 = fex2(NEG_K * fsqrt_a(q0));
                float w1 = fex2(NEG_K * fsqrt_a(q1));
                float w2 = fex2(NEG_K * fsqrt_a(q2));
                float w3 = fex2(NEG_K * fsqrt_a(q3));
                wfc[2 * j]     = bfpack(w0, w1);
                wfc[2 * j + 1] = bfpack(w2, w3);
            }

            // GEMM2(g): ACC += W_g . Mt[k-slice g]; B double-buffered in regs.
            // J=6 ldsm.x4 touches staged-but-stale rows 104-111; those two
            // fragments are never consumed.
            const uint32_t colg = ((uint32_t)(32 * g + bKb)) ^ bsw;
            {
                uint32_t b4[2][4];
                ldsm4(b4[0], mTile + (uint32_t)bRow * 128 + colg);
                #pragma unroll
                for (int J = 0; J < 7; J++) {
                    if (J < 6)
                        ldsm4(b4[(J + 1) & 1],
                              mTile + (uint32_t)(16 * (J + 1) + bRow) * 128 + colg);
                    const uint32_t* c4 = b4[J & 1];
                    mma16816(acc[2 * J], wfc, c4[0], c4[1]);
                    if (J < 6)
                        mma16816(acc[2 * J + 1], wfc, c4[2], c4[3]);
                }
            }
        }
        __syncthreads();
    }

    // ---- write k-split partials: slice = split*2 + ng ----
    {
        const int sp2 = split * 2 + ng;
        int rA = b0 + m0 + (lane >> 2);
        size_t baseA = ((size_t)sp2 * CONST_B + rA) * PSTRIDE;
        size_t baseB = baseA + (size_t)8 * PSTRIDE;
        #pragma unroll
        for (int jt = 0; jt < 13; jt++) {
            int c = 8 * jt + t4x2;
            if (c <= CONST_C) {
                g_part[baseA + c] = acc[jt][0];
                g_part[baseB + c] = acc[jt][2];
            }
            if (c + 1 <= CONST_C) {
                g_part[baseA + c + 1] = acc[jt][1];
                g_part[baseB + c + 1] = acc[jt][3];
            }
        }
    }
}

// ---------------------------------------------------------------------------
// reduce: deterministic sum over 18 partial slices + normalize.
// ---------------------------------------------------------------------------
__global__ void reduce_kernel(float* __restrict__ out) {
    int i = blockIdx.x * blockDim.x + threadIdx.x;
    if (i >= CONST_B * CONST_C) return;
    int b = i / CONST_C, c = i % CONST_C;
    float num = 0.f, den = 0.f;
    #pragma unroll
    for (int s = 0; s < NSPLIT2; s++) {
        const float* p = g_part + ((size_t)s * CONST_B + b) * PSTRIDE;
        num += p[c];
        den += p[CONST_C];
    }
    out[i] = num / den;
}

// ---------------------------------------------------------------------------
extern "C" void kernel_launch(void* const* d_in, const int* in_sizes, int n_in,
                              void* d_out, int out_size)
{
    const float* x = (const float*)d_in[0];   // [2048, 128]
    const float* A = (const float*)d_in[1];   // [100000, 128]
    const float* M = (const float*)d_in[2];   // [100000, 100]
    float* out = (float*)d_out;               // [2048, 100]

    cudaFuncSetAttribute(dsdm_mma, cudaFuncAttributeMaxDynamicSharedMemorySize,
                         SM_TOTAL);
    cudaFuncSetAttribute(prep_AM, cudaFuncAttributeMaxDynamicSharedMemorySize,
                         128 * 104 * 4);

    prep_AM<<<NA_BLOCKS + NMT_BLOCKS, 256, 128 * 104 * 4>>>(A, M);
    dsdm_mma<<<dim3(CONST_B / 128, NSPLIT), THREADS, SM_TOTAL>>>(x);
    reduce_kernel<<<(CONST_B * CONST_C + 255) / 256, 256>>>(out);
}

// round 15
// speedup vs baseline: 1.2698x; 1.0379x over previous
#include <cuda_runtime.h>
#include <cstdint>
#include <cstddef>

// ---------------------------------------------------------------------------
// DSDM classifier via mma.sync bf16, 512 threads (16 warps = 8 mg x 2 ng):
//   S = x . A^T ; w = exp(-sqrt(|x|^2+|A|^2-2S)/T) ; out = (W.M)/rowsum(W)
// x[2048,128], A[100000,128], M[100000,100], out[2048,100], T=2.
// Per warp: 16 m-rows, one 64-n half of GEMM1, matching 64-k half of GEMM2.
// B fragments double-buffered in registers; W register-resident; k-split
// partials -> deterministic reduce. Prep fused into one launch with
// conflict-free (105-stride) transpose staging and 32-row A blocks.
// ---------------------------------------------------------------------------

#define CONST_B   2048
#define CONST_D   128
#define CONST_N   100000
#define CONST_C   100

#define NSPLIT    9
#define NSPLIT2   18                  // NSPLIT * 2 (k-halves)
#define NPER      11136               // 87 * 128
#define NPAD      100096              // 782 * 128
#define THREADS   512
#define PSTRIDE   112
#define CT        104                 // staged class rows (>=101 needed)

#define NA_BLOCKS  (NPAD / 32)        // 3128 A-prep blocks (32 rows each)
#define NMT_BLOCKS (NPAD / 128)       // 782 Mt-prep blocks
#define MT_STRIDE  105                // staging row stride (gcd(105,32)=1)
#define PREP_SMEM  (128 * MT_STRIDE * 4)

// -(1 / (T * ln2)), T = 2
#define NEG_K     (-0.72134752044448169f)

// smem byte offsets
#define SM_XN     0                   // float[128]
#define SM_AN     512                 // 2 bufs x 128 floats
#define SM_X      2048                // 2 halves x 16384 (x tile, bf16 SW128)
#define SM_A      34816               // 2 bufs x (2 halves x 16384)
#define SM_MT     100352              // 2 bufs x (2 halves x 16384)
#define SM_TOTAL  165888

#define SWZ(b)    ((b) ^ (((b) >> 3) & 0x70))

// device scratch (allocation-free)
__device__ float g_anorm[NPAD];
__device__ __align__(256) unsigned short g_Abf[(size_t)CONST_N * CONST_D];
__device__ __align__(256) unsigned short g_Mt[(size_t)128 * NPAD];
__device__ float g_part[(size_t)NSPLIT2 * CONST_B * PSTRIDE];

// ---------------- asm helpers ----------------
__device__ __forceinline__ uint32_t smem_u32(const void* p) {
    uint32_t a;
    asm("{ .reg .u64 t; cvta.to.shared.u64 t, %1; cvt.u32.u64 %0, t; }"
        : "=r"(a) : "l"(p));
    return a;
}
__device__ __forceinline__ uint32_t bfpack(float lo, float hi) {
    uint32_t r;
    asm("cvt.rn.bf16x2.f32 %0, %1, %2;" : "=r"(r) : "f"(hi), "f"(lo));
    return r;
}
__device__ __forceinline__ float fsqrt_a(float x) {
    float r; asm("sqrt.approx.f32 %0, %1;" : "=f"(r) : "f"(x)); return r;
}
__device__ __forceinline__ float fex2(float x) {
    float r; asm("ex2.approx.f32 %0, %1;" : "=f"(r) : "f"(x)); return r;
}
__device__ __forceinline__ void ldsm4(uint32_t* r, uint32_t addr) {
    asm volatile("ldmatrix.sync.aligned.m8n8.x4.shared.b16 {%0,%1,%2,%3}, [%4];"
                 : "=r"(r[0]), "=r"(r[1]), "=r"(r[2]), "=r"(r[3]) : "r"(addr));
}
__device__ __forceinline__ void mma16816(float* c, const uint32_t* a,
                                         uint32_t b0, uint32_t b1) {
    asm volatile(
        "mma.sync.aligned.m16n8k16.row.col.f32.bf16.bf16.f32 "
        "{%0,%1,%2,%3}, {%4,%5,%6,%7}, {%8,%9}, {%0,%1,%2,%3};"
        : "+f"(c[0]), "+f"(c[1]), "+f"(c[2]), "+f"(c[3])
        : "r"(a[0]), "r"(a[1]), "r"(a[2]), "r"(a[3]), "r"(b0), "r"(b1));
}
__device__ __forceinline__ void cpasync16(uint32_t dst, const void* src) {
    asm volatile("cp.async.cg.shared.global [%0], [%1], 16;"
                 :: "r"(dst), "l"(src) : "memory");
}
#define CP_COMMIT asm volatile("cp.async.commit_group;" ::: "memory")
#define CP_WAIT1  asm volatile("cp.async.wait_group 1;" ::: "memory")
#define CP_WAIT0  asm volatile("cp.async.wait_group 0;" ::: "memory")

// ---------------------------------------------------------------------------
// prep_AM: fused prep. Blocks [0, NA_BLOCKS): |A_n|^2 fp32 + A -> bf16,
// 32 rows/block (padding rows get anorm = 1e30 -> w = 0).
// Blocks [NA_BLOCKS, +NMT_BLOCKS): M[n][c] fp32 -> g_Mt[c][n] bf16 via a
// conflict-free (stride-105) smem transpose; row 100 = 1.0, zero padding.
// ---------------------------------------------------------------------------
__global__ void prep_AM(const float* __restrict__ A, const float* __restrict__ M) {
    extern __shared__ float st[];     // Mt branch: [128][105]
    if (blockIdx.x < NA_BLOCKS) {
        const int lane  = threadIdx.x & 31;
        const int row0  = blockIdx.x * 32 + (threadIdx.x >> 5) * 4;
        #pragma unroll
        for (int r = 0; r < 4; r++) {
            int row = row0 + r;
            if (row >= CONST_N) {
                if (row < NPAD && lane == 0) g_anorm[row] = 1e30f;
                continue;
            }
            float4 v = reinterpret_cast<const float4*>(A + (size_t)row * CONST_D)[lane];
            float s = v.x * v.x + v.y * v.y + v.z * v.z + v.w * v.w;
            #pragma unroll
            for (int o = 16; o; o >>= 1) s += __shfl_xor_sync(0xffffffffu, s, o);
            if (lane == 0) g_anorm[row] = s;
            uint2 p = make_uint2(bfpack(v.x, v.y), bfpack(v.z, v.w));
            reinterpret_cast<uint2*>(g_Abf + (size_t)row * CONST_D)[lane] = p;
        }
        return;
    }
    // ---- Mt transpose branch (conflict-free staging) ----
    const int tid = threadIdx.x;
    const int t0  = (blockIdx.x - NA_BLOCKS) * 128;
    for (int idx = tid; idx < 128 * 25; idx += 256) {
        int r = idx / 25, q = idx % 25;
        int n = t0 + r;
        float4 v = make_float4(0.f, 0.f, 0.f, 0.f);
        if (n < CONST_N)
            v = reinterpret_cast<const float4*>(M + (size_t)n * CONST_C)[q];
        st[r * MT_STRIDE + q * 4 + 0] = v.x;
        st[r * MT_STRIDE + q * 4 + 1] = v.y;
        st[r * MT_STRIDE + q * 4 + 2] = v.z;
        st[r * MT_STRIDE + q * 4 + 3] = v.w;
    }
    __syncthreads();
    for (int idx = tid; idx < 128 * 16; idx += 256) {
        int c = idx >> 4, nq = idx & 15;
        uint32_t h[4];
        #pragma unroll
        for (int j = 0; j < 4; j++) {
            int nl = nq * 8 + j * 2;
            float f0, f1;
            if (c < CONST_C) {
                f0 = st[nl * MT_STRIDE + c];
                f1 = st[(nl + 1) * MT_STRIDE + c];
            } else if (c == CONST_C) {
                f0 = (t0 + nl     < CONST_N) ? 1.f : 0.f;
                f1 = (t0 + nl + 1 < CONST_N) ? 1.f : 0.f;
            } else { f0 = 0.f; f1 = 0.f; }
            h[j] = bfpack(f0, f1);
        }
        reinterpret_cast<uint4*>(g_Mt + (size_t)c * NPAD + t0)[nq] =
            make_uint4(h[0], h[1], h[2], h[3]);
    }
}

// ---------------------------------------------------------------------------
// cp.async staging of one 128-address chunk (512 threads).
// ---------------------------------------------------------------------------
__device__ __forceinline__ void stage_chunk(uint32_t sb, int n0, int nEnd,
                                            int buf, int tid) {
    const int q  = tid & 3;            // 64-byte quarter of a 256-B row
    const int hf = q >> 1;             // 128-B half
    const uint32_t qoff = (uint32_t)(q & 1) * 64;
    {   // A chunk: row nl (0..127), SW128 within each 128-B half-row
        int nl = tid >> 2;
        int nIdx = n0 + nl; if (nIdx >= nEnd) nIdx = nEnd - 1;
        const char* src = (const char*)(g_Abf + (size_t)nIdx * CONST_D + hf * 64)
                          + qoff;
        uint32_t dst = sb + SM_A + buf * 32768 + hf * 16384 + (uint32_t)nl * 128;
        uint32_t sw = (uint32_t)(nl & 7) << 4;
        #pragma unroll
        for (int j = 0; j < 4; j++)
            cpasync16(dst + ((qoff + (uint32_t)(j * 16)) ^ sw), src + j * 16);
    }
    {   // Mt chunk: class row c (< CT)
        int c = tid >> 2;
        if (c < CT) {
            const char* src = (const char*)(g_Mt + (size_t)c * NPAD + n0 + hf * 64)
                              + qoff;
            uint32_t dst = sb + SM_MT + buf * 32768 + hf * 16384 + (uint32_t)c * 128;
            uint32_t sw = (uint32_t)(c & 7) << 4;
            #pragma unroll
            for (int j = 0; j < 4; j++)
                cpasync16(dst + ((qoff + (uint32_t)(j * 16)) ^ sw), src + j * 16);
        }
    }
    if (tid < 32)   // anorms (padded with 1e30 -> w=0, no OOB)
        cpasync16(sb + SM_AN + buf * 512 + tid * 16,
                  (const char*)(g_anorm + n0) + tid * 16);
}

// ---------------------------------------------------------------------------
// main fused kernel: grid (16, 9), 512 threads = 8 m-groups x 2 n/k-halves.
// ---------------------------------------------------------------------------
__global__ void __launch_bounds__(THREADS, 1)
dsdm_mma(const float* __restrict__ x)
{
    extern __shared__ char smem[];
    const uint32_t sb = smem_u32(smem);
    const int tid  = threadIdx.x;
    const int warp = tid >> 5, lane = tid & 31;
    const int mg   = warp >> 1;        // m-group: rows [16mg, 16mg+16)
    const int ng   = warp & 1;         // n/k half
    const int m0   = mg * 16;
    const int b0   = blockIdx.x * 128;
    const int split = blockIdx.y;
    const int nBeg = split * NPER;
    const int nEnd = (nBeg + NPER < CONST_N) ? nBeg + NPER : CONST_N;
    const int nchunks = (nEnd - nBeg + 127) >> 7;

    float* xn_s = reinterpret_cast<float*>(smem + SM_XN);

    // ---- stage x tile (bf16 SW128 halves) + row norms ----
    for (int r = warp; r < 128; r += 16) {
        float4 v = reinterpret_cast<const float4*>(x + (size_t)(b0 + r) * CONST_D)[lane];
        float sq = v.x * v.x + v.y * v.y + v.z * v.z + v.w * v.w;
        #pragma unroll
        for (int o = 16; o; o >>= 1) sq += __shfl_xor_sync(0xffffffffu, sq, o);
        if (lane == 0) xn_s[r] = sq;
        uint2 p = make_uint2(bfpack(v.x, v.y), bfpack(v.z, v.w));
        uint32_t off = (uint32_t)r * 128 + (lane & 15) * 8;
        *reinterpret_cast<uint2*>(smem + SM_X + (lane >> 4) * 16384 + SWZ(off)) = p;
    }

    // prefetch chunk 0
    stage_chunk(sb, nBeg, nEnd, 0, tid);
    CP_COMMIT;
    __syncthreads();

    // ---- X fragments: 16m x 128k A-operands, register-resident ----
    uint32_t xa[8][4];
    {
        int aRow = (lane & 7) + ((lane >> 3) & 1) * 8;
        int aKb  = (lane >> 4) * 16;
        uint32_t swr = (uint32_t)(aRow & 7) << 4;
        uint32_t rb  = sb + SM_X + (uint32_t)(m0 + aRow) * 128;
        #pragma unroll
        for (int kk = 0; kk < 8; kk++) {
            uint32_t col = (uint32_t)(((32 * kk) & 127) + aKb) ^ swr;
            ldsm4(xa[kk], rb + (kk >> 2) * 16384 + col);
        }
    }
    const float xn0 = xn_s[m0 + (lane >> 2)];
    const float xn1 = xn_s[m0 + 8 + (lane >> 2)];

    // B-operand ldmatrix lane map
    const int bRow = (lane & 7) + ((lane >> 4) & 1) * 8;
    const int bKb  = ((lane >> 3) & 1) * 16;
    const uint32_t bsw = (uint32_t)(bRow & 7) << 4;
    uint32_t bcol[8];
    #pragma unroll
    for (int kk = 0; kk < 8; kk++)
        bcol[kk] = (uint32_t)(((32 * kk) & 127) + bKb) ^ bsw;

    const int t4x2 = (lane & 3) * 2;

    float acc[13][4];                  // 16m x 104c k-partial
    #pragma unroll
    for (int j = 0; j < 13; j++)
        #pragma unroll
        for (int qq = 0; qq < 4; qq++) acc[j][qq] = 0.f;

    for (int ch = 0; ch < nchunks; ch++) {
        if (ch + 1 < nchunks) {
            stage_chunk(sb, nBeg + (ch + 1) * 128, nEnd, (ch + 1) & 1, tid);
            CP_COMMIT;
            CP_WAIT1;
        } else {
            CP_WAIT0;
        }
        __syncthreads();

        const int buf = ch & 1;
        const uint32_t aTile = sb + SM_A + buf * 32768;
        const uint32_t mTile = sb + SM_MT + buf * 32768 + ng * 16384;
        const float* an_b = reinterpret_cast<const float*>(smem + SM_AN + buf * 512);

        #pragma unroll
        for (int g = 0; g < 4; g++) {
            const int nb = 64 * ng + 16 * g;

            // GEMM1 slice: S[16m x 16n] (k = 128), B double-buffered in regs
            float sacc[2][4];
            #pragma unroll
            for (int j = 0; j < 2; j++)
                #pragma unroll
                for (int qq = 0; qq < 4; qq++) sacc[j][qq] = 0.f;
            {
                uint32_t rowb = aTile + (uint32_t)(nb + bRow) * 128;
                uint32_t b4[2][4];
                ldsm4(b4[0], rowb + bcol[0]);
                #pragma unroll
                for (int kk = 0; kk < 8; kk++) {
                    if (kk < 7)
                        ldsm4(b4[(kk + 1) & 1],
                              rowb + ((kk + 1) >> 2) * 16384 + bcol[kk + 1]);
                    const uint32_t* c4 = b4[kk & 1];
                    mma16816(sacc[0], xa[kk], c4[0], c4[1]);
                    mma16816(sacc[1], xa[kk], c4[2], c4[3]);
                }
            }

            // epilogue: w = exp2(-K*sqrt(xn+an-2S)) -> A-frag wfc (regs only)
            uint32_t wfc[4];
            #pragma unroll
            for (int j = 0; j < 2; j++) {
                float2 anv = *reinterpret_cast<const float2*>(an_b + nb + 8 * j + t4x2);
                float q0 = fmaxf(fmaf(-2.f, sacc[j][0], xn0 + anv.x), 0.f);
                float q1 = fmaxf(fmaf(-2.f, sacc[j][1], xn0 + anv.y), 0.f);
                float q2 = fmaxf(fmaf(-2.f, sacc[j][2], xn1 + anv.x), 0.f);
                float q3 = fmaxf(fmaf(-2.f, sacc[j][3], xn1 + anv.y), 0.f);
                float w0 = fex2(NEG_K * fsqrt_a(q0));
                float w1 = fex2(NEG_K * fsqrt_a(q1));
                float w2 = fex2(NEG_K * fsqrt_a(q2));
                float w3 = fex2(NEG_K * fsqrt_a(q3));
                wfc[2 * j]     = bfpack(w0, w1);
                wfc[2 * j + 1] = bfpack(w2, w3);
            }

            // GEMM2(g): ACC += W_g . Mt[k-slice g]; B double-buffered in regs.
            // J=6 ldsm.x4 touches staged-but-stale rows 104-111; those two
            // fragments are never consumed.
            const uint32_t colg = ((uint32_t)(32 * g + bKb)) ^ bsw;
            {
                uint32_t b4[2][4];
                ldsm4(b4[0], mTile + (uint32_t)bRow * 128 + colg);
                #pragma unroll
                for (int J = 0; J < 7; J++) {
                    if (J < 6)
                        ldsm4(b4[(J + 1) & 1],
                              mTile + (uint32_t)(16 * (J + 1) + bRow) * 128 + colg);
                    const uint32_t* c4 = b4[J & 1];
                    mma16816(acc[2 * J], wfc, c4[0], c4[1]);
                    if (J < 6)
                        mma16816(acc[2 * J + 1], wfc, c4[2], c4[3]);
                }
            }
        }
        __syncthreads();
    }

    // ---- write k-split partials: slice = split*2 + ng ----
    {
        const int sp2 = split * 2 + ng;
        int rA = b0 + m0 + (lane >> 2);
        size_t baseA = ((size_t)sp2 * CONST_B + rA) * PSTRIDE;
        size_t baseB = baseA + (size_t)8 * PSTRIDE;
        #pragma unroll
        for (int jt = 0; jt < 13; jt++) {
            int c = 8 * jt + t4x2;
            if (c <= CONST_C) {
                g_part[baseA + c] = acc[jt][0];
                g_part[baseB + c] = acc[jt][2];
            }
            if (c + 1 <= CONST_C) {
                g_part[baseA + c + 1] = acc[jt][1];
                g_part[baseB + c + 1] = acc[jt][3];
            }
        }
    }
}

// ---------------------------------------------------------------------------
// reduce: deterministic sum over 18 partial slices + normalize.
// ---------------------------------------------------------------------------
__global__ void reduce_kernel(float* __restrict__ out) {
    int i = blockIdx.x * blockDim.x + threadIdx.x;
    if (i >= CONST_B * CONST_C) return;
    int b = i / CONST_C, c = i % CONST_C;
    float num = 0.f, den = 0.f;
    #pragma unroll
    for (int s = 0; s < NSPLIT2; s++) {
        const float* p = g_part + ((size_t)s * CONST_B + b) * PSTRIDE;
        num += p[c];
        den += p[CONST_C];
    }
    out[i] = num / den;
}

// ---------------------------------------------------------------------------
extern "C" void kernel_launch(void* const* d_in, const int* in_sizes, int n_in,
                              void* d_out, int out_size)
{
    const float* x = (const float*)d_in[0];   // [2048, 128]
    const float* A = (const float*)d_in[1];   // [100000, 128]
    const float* M = (const float*)d_in[2];   // [100000, 100]
    float* out = (float*)d_out;               // [2048, 100]

    cudaFuncSetAttribute(dsdm_mma, cudaFuncAttributeMaxDynamicSharedMemorySize,
                         SM_TOTAL);
    cudaFuncSetAttribute(prep_AM, cudaFuncAttributeMaxDynamicSharedMemorySize,
                         PREP_SMEM);

    prep_AM<<<NA_BLOCKS + NMT_BLOCKS, 256, PREP_SMEM>>>(A, M);
    dsdm_mma<<<dim3(CONST_B / 128, NSPLIT), THREADS, SM_TOTAL>>>(x);
    reduce_kernel<<<(CONST_B * CONST_C + 255) / 256, 256>>>(out);
}

// round 16
// speedup vs baseline: 1.3196x; 1.0393x over previous
#include <cuda_runtime.h>
#include <cstdint>
#include <cstddef>

// ---------------------------------------------------------------------------
// DSDM classifier via mma.sync bf16, 512 threads (16 warps = 8 mg x 2 ng):
//   S = x . A^T ; w = exp(-sqrt(|x|^2+|A|^2-2S)/T) ; out = (W.M)/rowsum(W)
// x[2048,128], A[100000,128], M[100000,100], out[2048,100], T=2.
// Main loop at the legacy-mma.sync floor; this round: prep occupancy fix
// (32-row Mt tiles -> 13.4 KB smem) + float4-vectorized reduce.
// ---------------------------------------------------------------------------

#define CONST_B   2048
#define CONST_D   128
#define CONST_N   100000
#define CONST_C   100

#define NSPLIT    9
#define NSPLIT2   18                  // NSPLIT * 2 (k-halves)
#define NPER      11136               // 87 * 128
#define NPAD      100096              // 782 * 128
#define THREADS   512
#define PSTRIDE   112
#define CT        104                 // staged class rows (>=101 needed)

#define NA_BLOCKS  (NPAD / 32)        // 3128 A-prep blocks (32 rows each)
#define NMT_BLOCKS (NPAD / 32)        // 3128 Mt-prep blocks (32 n each)
#define MT_STRIDE  105                // staging row stride (gcd(105,32)=1)
#define PREP_SMEM  (32 * MT_STRIDE * 4)   // 13440 B

// -(1 / (T * ln2)), T = 2
#define NEG_K     (-0.72134752044448169f)

// smem byte offsets (main kernel)
#define SM_XN     0                   // float[128]
#define SM_AN     512                 // 2 bufs x 128 floats
#define SM_X      2048                // 2 halves x 16384 (x tile, bf16 SW128)
#define SM_A      34816               // 2 bufs x (2 halves x 16384)
#define SM_MT     100352              // 2 bufs x (2 halves x 16384)
#define SM_TOTAL  165888

#define SWZ(b)    ((b) ^ (((b) >> 3) & 0x70))

// device scratch (allocation-free)
__device__ float g_anorm[NPAD];
__device__ __align__(256) unsigned short g_Abf[(size_t)CONST_N * CONST_D];
__device__ __align__(256) unsigned short g_Mt[(size_t)128 * NPAD];
__device__ float g_part[(size_t)NSPLIT2 * CONST_B * PSTRIDE];

// ---------------- asm helpers ----------------
__device__ __forceinline__ uint32_t smem_u32(const void* p) {
    uint32_t a;
    asm("{ .reg .u64 t; cvta.to.shared.u64 t, %1; cvt.u32.u64 %0, t; }"
        : "=r"(a) : "l"(p));
    return a;
}
__device__ __forceinline__ uint32_t bfpack(float lo, float hi) {
    uint32_t r;
    asm("cvt.rn.bf16x2.f32 %0, %1, %2;" : "=r"(r) : "f"(hi), "f"(lo));
    return r;
}
__device__ __forceinline__ float fsqrt_a(float x) {
    float r; asm("sqrt.approx.f32 %0, %1;" : "=f"(r) : "f"(x)); return r;
}
__device__ __forceinline__ float fex2(float x) {
    float r; asm("ex2.approx.f32 %0, %1;" : "=f"(r) : "f"(x)); return r;
}
__device__ __forceinline__ void ldsm4(uint32_t* r, uint32_t addr) {
    asm volatile("ldmatrix.sync.aligned.m8n8.x4.shared.b16 {%0,%1,%2,%3}, [%4];"
                 : "=r"(r[0]), "=r"(r[1]), "=r"(r[2]), "=r"(r[3]) : "r"(addr));
}
__device__ __forceinline__ void mma16816(float* c, const uint32_t* a,
                                         uint32_t b0, uint32_t b1) {
    asm volatile(
        "mma.sync.aligned.m16n8k16.row.col.f32.bf16.bf16.f32 "
        "{%0,%1,%2,%3}, {%4,%5,%6,%7}, {%8,%9}, {%0,%1,%2,%3};"
        : "+f"(c[0]), "+f"(c[1]), "+f"(c[2]), "+f"(c[3])
        : "r"(a[0]), "r"(a[1]), "r"(a[2]), "r"(a[3]), "r"(b0), "r"(b1));
}
__device__ __forceinline__ void cpasync16(uint32_t dst, const void* src) {
    asm volatile("cp.async.cg.shared.global [%0], [%1], 16;"
                 :: "r"(dst), "l"(src) : "memory");
}
#define CP_COMMIT asm volatile("cp.async.commit_group;" ::: "memory")
#define CP_WAIT1  asm volatile("cp.async.wait_group 1;" ::: "memory")
#define CP_WAIT0  asm volatile("cp.async.wait_group 0;" ::: "memory")

// ---------------------------------------------------------------------------
// prep_AM: fused prep, small smem for high occupancy.
// Blocks [0, NA_BLOCKS): |A_n|^2 fp32 + A -> bf16, 32 rows/block
// (padding rows get anorm = 1e30 -> w = 0).
// Blocks [NA_BLOCKS, +NMT_BLOCKS): 32-n tile of M -> g_Mt[c][n] bf16 via a
// conflict-free (stride-105) smem transpose; row 100 = 1.0, zero padding;
// only the CT class rows consumed by the main kernel are written.
// ---------------------------------------------------------------------------
__global__ void prep_AM(const float* __restrict__ A, const float* __restrict__ M) {
    extern __shared__ float st[];     // Mt branch: [32][105]
    if (blockIdx.x < NA_BLOCKS) {
        const int lane  = threadIdx.x & 31;
        const int row0  = blockIdx.x * 32 + (threadIdx.x >> 5) * 4;
        #pragma unroll
        for (int r = 0; r < 4; r++) {
            int row = row0 + r;
            if (row >= CONST_N) {
                if (row < NPAD && lane == 0) g_anorm[row] = 1e30f;
                continue;
            }
            float4 v = reinterpret_cast<const float4*>(A + (size_t)row * CONST_D)[lane];
            float s = v.x * v.x + v.y * v.y + v.z * v.z + v.w * v.w;
            #pragma unroll
            for (int o = 16; o; o >>= 1) s += __shfl_xor_sync(0xffffffffu, s, o);
            if (lane == 0) g_anorm[row] = s;
            uint2 p = make_uint2(bfpack(v.x, v.y), bfpack(v.z, v.w));
            reinterpret_cast<uint2*>(g_Abf + (size_t)row * CONST_D)[lane] = p;
        }
        return;
    }
    // ---- Mt transpose branch: 32 n-rows, conflict-free staging ----
    const int tid = threadIdx.x;
    const int t0  = (blockIdx.x - NA_BLOCKS) * 32;
    for (int idx = tid; idx < 32 * 25; idx += 256) {
        int r = idx / 25, q = idx % 25;
        int n = t0 + r;
        float4 v = make_float4(0.f, 0.f, 0.f, 0.f);
        if (n < CONST_N)
            v = reinterpret_cast<const float4*>(M + (size_t)n * CONST_C)[q];
        st[r * MT_STRIDE + q * 4 + 0] = v.x;
        st[r * MT_STRIDE + q * 4 + 1] = v.y;
        st[r * MT_STRIDE + q * 4 + 2] = v.z;
        st[r * MT_STRIDE + q * 4 + 3] = v.w;
    }
    __syncthreads();
    // write CT class rows x 32 n (each thread: one 16-n half of one c row)
    for (int idx = tid; idx < CT * 2; idx += 256) {
        int c = idx >> 1, half = idx & 1;
        uint32_t h[8];
        #pragma unroll
        for (int j = 0; j < 8; j++) {
            int nl = half * 16 + j * 2;
            float f0, f1;
            if (c < CONST_C) {
                f0 = st[nl * MT_STRIDE + c];
                f1 = st[(nl + 1) * MT_STRIDE + c];
            } else if (c == CONST_C) {
                f0 = (t0 + nl     < CONST_N) ? 1.f : 0.f;
                f1 = (t0 + nl + 1 < CONST_N) ? 1.f : 0.f;
            } else { f0 = 0.f; f1 = 0.f; }
            h[j] = bfpack(f0, f1);
        }
        uint4* dst = reinterpret_cast<uint4*>(g_Mt + (size_t)c * NPAD + t0 + half * 16);
        dst[0] = make_uint4(h[0], h[1], h[2], h[3]);
        dst[1] = make_uint4(h[4], h[5], h[6], h[7]);
    }
}

// ---------------------------------------------------------------------------
// cp.async staging of one 128-address chunk (512 threads).
// ---------------------------------------------------------------------------
__device__ __forceinline__ void stage_chunk(uint32_t sb, int n0, int nEnd,
                                            int buf, int tid) {
    const int q  = tid & 3;            // 64-byte quarter of a 256-B row
    const int hf = q >> 1;             // 128-B half
    const uint32_t qoff = (uint32_t)(q & 1) * 64;
    {   // A chunk: row nl (0..127), SW128 within each 128-B half-row
        int nl = tid >> 2;
        int nIdx = n0 + nl; if (nIdx >= nEnd) nIdx = nEnd - 1;
        const char* src = (const char*)(g_Abf + (size_t)nIdx * CONST_D + hf * 64)
                          + qoff;
        uint32_t dst = sb + SM_A + buf * 32768 + hf * 16384 + (uint32_t)nl * 128;
        uint32_t sw = (uint32_t)(nl & 7) << 4;
        #pragma unroll
        for (int j = 0; j < 4; j++)
            cpasync16(dst + ((qoff + (uint32_t)(j * 16)) ^ sw), src + j * 16);
    }
    {   // Mt chunk: class row c (< CT)
        int c = tid >> 2;
        if (c < CT) {
            const char* src = (const char*)(g_Mt + (size_t)c * NPAD + n0 + hf * 64)
                              + qoff;
            uint32_t dst = sb + SM_MT + buf * 32768 + hf * 16384 + (uint32_t)c * 128;
            uint32_t sw = (uint32_t)(c & 7) << 4;
            #pragma unroll
            for (int j = 0; j < 4; j++)
                cpasync16(dst + ((qoff + (uint32_t)(j * 16)) ^ sw), src + j * 16);
        }
    }
    if (tid < 32)   // anorms (padded with 1e30 -> w=0, no OOB)
        cpasync16(sb + SM_AN + buf * 512 + tid * 16,
                  (const char*)(g_anorm + n0) + tid * 16);
}

// ---------------------------------------------------------------------------
// main fused kernel: grid (16, 9), 512 threads = 8 m-groups x 2 n/k-halves.
// ---------------------------------------------------------------------------
__global__ void __launch_bounds__(THREADS, 1)
dsdm_mma(const float* __restrict__ x)
{
    extern __shared__ char smem[];
    const uint32_t sb = smem_u32(smem);
    const int tid  = threadIdx.x;
    const int warp = tid >> 5, lane = tid & 31;
    const int mg   = warp >> 1;        // m-group: rows [16mg, 16mg+16)
    const int ng   = warp & 1;         // n/k half
    const int m0   = mg * 16;
    const int b0   = blockIdx.x * 128;
    const int split = blockIdx.y;
    const int nBeg = split * NPER;
    const int nEnd = (nBeg + NPER < CONST_N) ? nBeg + NPER : CONST_N;
    const int nchunks = (nEnd - nBeg + 127) >> 7;

    float* xn_s = reinterpret_cast<float*>(smem + SM_XN);

    // ---- stage x tile (bf16 SW128 halves) + row norms ----
    for (int r = warp; r < 128; r += 16) {
        float4 v = reinterpret_cast<const float4*>(x + (size_t)(b0 + r) * CONST_D)[lane];
        float sq = v.x * v.x + v.y * v.y + v.z * v.z + v.w * v.w;
        #pragma unroll
        for (int o = 16; o; o >>= 1) sq += __shfl_xor_sync(0xffffffffu, sq, o);
        if (lane == 0) xn_s[r] = sq;
        uint2 p = make_uint2(bfpack(v.x, v.y), bfpack(v.z, v.w));
        uint32_t off = (uint32_t)r * 128 + (lane & 15) * 8;
        *reinterpret_cast<uint2*>(smem + SM_X + (lane >> 4) * 16384 + SWZ(off)) = p;
    }

    // prefetch chunk 0
    stage_chunk(sb, nBeg, nEnd, 0, tid);
    CP_COMMIT;
    __syncthreads();

    // ---- X fragments: 16m x 128k A-operands, register-resident ----
    uint32_t xa[8][4];
    {
        int aRow = (lane & 7) + ((lane >> 3) & 1) * 8;
        int aKb  = (lane >> 4) * 16;
        uint32_t swr = (uint32_t)(aRow & 7) << 4;
        uint32_t rb  = sb + SM_X + (uint32_t)(m0 + aRow) * 128;
        #pragma unroll
        for (int kk = 0; kk < 8; kk++) {
            uint32_t col = (uint32_t)(((32 * kk) & 127) + aKb) ^ swr;
            ldsm4(xa[kk], rb + (kk >> 2) * 16384 + col);
        }
    }
    const float xn0 = xn_s[m0 + (lane >> 2)];
    const float xn1 = xn_s[m0 + 8 + (lane >> 2)];

    // B-operand ldmatrix lane map
    const int bRow = (lane & 7) + ((lane >> 4) & 1) * 8;
    const int bKb  = ((lane >> 3) & 1) * 16;
    const uint32_t bsw = (uint32_t)(bRow & 7) << 4;
    uint32_t bcol[8];
    #pragma unroll
    for (int kk = 0; kk < 8; kk++)
        bcol[kk] = (uint32_t)(((32 * kk) & 127) + bKb) ^ bsw;

    const int t4x2 = (lane & 3) * 2;

    float acc[13][4];                  // 16m x 104c k-partial
    #pragma unroll
    for (int j = 0; j < 13; j++)
        #pragma unroll
        for (int qq = 0; qq < 4; qq++) acc[j][qq] = 0.f;

    for (int ch = 0; ch < nchunks; ch++) {
        if (ch + 1 < nchunks) {
            stage_chunk(sb, nBeg + (ch + 1) * 128, nEnd, (ch + 1) & 1, tid);
            CP_COMMIT;
            CP_WAIT1;
        } else {
            CP_WAIT0;
        }
        __syncthreads();

        const int buf = ch & 1;
        const uint32_t aTile = sb + SM_A + buf * 32768;
        const uint32_t mTile = sb + SM_MT + buf * 32768 + ng * 16384;
        const float* an_b = reinterpret_cast<const float*>(smem + SM_AN + buf * 512);

        #pragma unroll
        for (int g = 0; g < 4; g++) {
            const int nb = 64 * ng + 16 * g;

            // GEMM1 slice: S[16m x 16n] (k = 128), B double-buffered in regs
            float sacc[2][4];
            #pragma unroll
            for (int j = 0; j < 2; j++)
                #pragma unroll
                for (int qq = 0; qq < 4; qq++) sacc[j][qq] = 0.f;
            {
                uint32_t rowb = aTile + (uint32_t)(nb + bRow) * 128;
                uint32_t b4[2][4];
                ldsm4(b4[0], rowb + bcol[0]);
                #pragma unroll
                for (int kk = 0; kk < 8; kk++) {
                    if (kk < 7)
                        ldsm4(b4[(kk + 1) & 1],
                              rowb + ((kk + 1) >> 2) * 16384 + bcol[kk + 1]);
                    const uint32_t* c4 = b4[kk & 1];
                    mma16816(sacc[0], xa[kk], c4[0], c4[1]);
                    mma16816(sacc[1], xa[kk], c4[2], c4[3]);
                }
            }

            // epilogue: w = exp2(-K*sqrt(xn+an-2S)) -> A-frag wfc (regs only)
            uint32_t wfc[4];
            #pragma unroll
            for (int j = 0; j < 2; j++) {
                float2 anv = *reinterpret_cast<const float2*>(an_b + nb + 8 * j + t4x2);
                float q0 = fmaxf(fmaf(-2.f, sacc[j][0], xn0 + anv.x), 0.f);
                float q1 = fmaxf(fmaf(-2.f, sacc[j][1], xn0 + anv.y), 0.f);
                float q2 = fmaxf(fmaf(-2.f, sacc[j][2], xn1 + anv.x), 0.f);
                float q3 = fmaxf(fmaf(-2.f, sacc[j][3], xn1 + anv.y), 0.f);
                float w0 = fex2(NEG_K * fsqrt_a(q0));
                float w1 = fex2(NEG_K * fsqrt_a(q1));
                float w2 = fex2(NEG_K * fsqrt_a(q2));
                float w3 = fex2(NEG_K * fsqrt_a(q3));
                wfc[2 * j]     = bfpack(w0, w1);
                wfc[2 * j + 1] = bfpack(w2, w3);
            }

            // GEMM2(g): ACC += W_g . Mt[k-slice g]; B double-buffered in regs.
            // J=6 ldsm.x4 touches staged-but-stale rows 104-111; those two
            // fragments are never consumed.
            const uint32_t colg = ((uint32_t)(32 * g + bKb)) ^ bsw;
            {
                uint32_t b4[2][4];
                ldsm4(b4[0], mTile + (uint32_t)bRow * 128 + colg);
                #pragma unroll
                for (int J = 0; J < 7; J++) {
                    if (J < 6)
                        ldsm4(b4[(J + 1) & 1],
                              mTile + (uint32_t)(16 * (J + 1) + bRow) * 128 + colg);
                    const uint32_t* c4 = b4[J & 1];
                    mma16816(acc[2 * J], wfc, c4[0], c4[1]);
                    if (J < 6)
                        mma16816(acc[2 * J + 1], wfc, c4[2], c4[3]);
                }
            }
        }
        __syncthreads();
    }

    // ---- write k-split partials: slice = split*2 + ng ----
    {
        const int sp2 = split * 2 + ng;
        int rA = b0 + m0 + (lane >> 2);
        size_t baseA = ((size_t)sp2 * CONST_B + rA) * PSTRIDE;
        size_t baseB = baseA + (size_t)8 * PSTRIDE;
        #pragma unroll
        for (int jt = 0; jt < 13; jt++) {
            int c = 8 * jt + t4x2;
            if (c <= CONST_C) {
                g_part[baseA + c] = acc[jt][0];
                g_part[baseB + c] = acc[jt][2];
            }
            if (c + 1 <= CONST_C) {
                g_part[baseA + c + 1] = acc[jt][1];
                g_part[baseB + c + 1] = acc[jt][3];
            }
        }
    }
}

// ---------------------------------------------------------------------------
// reduce: deterministic sum over 18 partial slices + normalize, float4 lanes.
// Thread i handles batch row b = i/25, classes [4q, 4q+4), q = i%25.
// ---------------------------------------------------------------------------
__global__ void reduce_kernel(float* __restrict__ out) {
    int i = blockIdx.x * blockDim.x + threadIdx.x;
    if (i >= CONST_B * 25) return;
    int b = i / 25, q = i % 25;
    float4 num = make_float4(0.f, 0.f, 0.f, 0.f);
    float den = 0.f;
    #pragma unroll
    for (int s = 0; s < NSPLIT2; s++) {
        const float* p = g_part + ((size_t)s * CONST_B + b) * PSTRIDE;
        float4 v = *reinterpret_cast<const float4*>(p + q * 4);
        num.x += v.x; num.y += v.y; num.z += v.z; num.w += v.w;
        den += p[CONST_C];
    }
    float inv = 1.f / den;
    float4 r = make_float4(num.x * inv, num.y * inv, num.z * inv, num.w * inv);
    *reinterpret_cast<float4*>(out + (size_t)b * CONST_C + q * 4) = r;
}

// ---------------------------------------------------------------------------
extern "C" void kernel_launch(void* const* d_in, const int* in_sizes, int n_in,
                              void* d_out, int out_size)
{
    const float* x = (const float*)d_in[0];   // [2048, 128]
    const float* A = (const float*)d_in[1];   // [100000, 128]
    const float* M = (const float*)d_in[2];   // [100000, 100]
    float* out = (float*)d_out;               // [2048, 100]

    cudaFuncSetAttribute(dsdm_mma, cudaFuncAttributeMaxDynamicSharedMemorySize,
                         SM_TOTAL);

    prep_AM<<<NA_BLOCKS + NMT_BLOCKS, 256, PREP_SMEM>>>(A, M);
    dsdm_mma<<<dim3(CONST_B / 128, NSPLIT), THREADS, SM_TOTAL>>>(x);
    reduce_kernel<<<(CONST_B * 25 + 255) / 256, 256>>>(out);
}